// round 14
// baseline (speedup 1.0000x reference)
#include <cuda_runtime.h>

typedef unsigned long long ull;

// ---------------- static problem config ----------------
#define M_TOK   262144      // 8 * 64 * 512 tokens
#define C_DIM   192
#define C3      576         // 3*C
#define HID     768
#define NHEADS  6
#define HD      32
#define NWIN    32          // 4*8 tokens per window

// ---------------- scratch (module-load allocated, ~2 GB) ----------------
__device__ float g_xw  [(size_t)M_TOK * C_DIM];   // LN1(win) and later LN2(x1)
__device__ float g_qkv [(size_t)M_TOK * C3];
__device__ float g_attn[(size_t)M_TOK * C_DIM];
__device__ float g_x1  [(size_t)M_TOK * C_DIM];
__device__ float g_hid [(size_t)M_TOK * HID];

// ---------------- packed f32x2 helpers (B300 FFMA2 path) ----------------
__device__ __forceinline__ ull pack2(float lo, float hi) {
    ull r;
    asm("mov.b64 %0, {%1, %2};" : "=l"(r) : "f"(lo), "f"(hi));
    return r;
}
__device__ __forceinline__ void unpack2(ull v, float& lo, float& hi) {
    asm("mov.b64 {%0, %1}, %2;" : "=f"(lo), "=f"(hi) : "l"(v));
}
__device__ __forceinline__ ull fma2(ull a, ull b, ull c) {
    ull r;
    asm("fma.rn.f32x2 %0, %1, %2, %3;" : "=l"(r) : "l"(a), "l"(b), "l"(c));
    return r;
}

// window-layout row m  ->  original token index (shift gather == scatter map)
__device__ __forceinline__ int orig_index(int m) {
    int bb  = m >> 15;          // / 32768 tokens per batch
    int rem = m & 32767;
    int wloc = rem >> 5;        // window within batch (0..1023)
    int t    = rem & 31;        // token within window
    int iwh = wloc >> 6;        // 0..15
    int iww = wloc & 63;        // 0..63
    int hs = iwh * 4 + (t >> 3);
    int ws = iww * 8 + (t & 7);
    int h = hs + 2; if (h >= 64)  h -= 64;
    int w = ws + 4; if (w >= 512) w -= 512;
    return (bb << 15) + (h << 9) + w;
}

// ---------------- LayerNorm (warp per row), optional shifted-window gather --
// mode 0: dst row = window layout, src = xin[orig_index(row)]   (LN1)
// mode 1: dst row = token layout,  src = g_x1[row]              (LN2)
__global__ __launch_bounds__(128) void ln_kernel(
    const float* __restrict__ xin, const float* __restrict__ gg,
    const float* __restrict__ bb, int mode)
{
    int warp = threadIdx.x >> 5;
    int lane = threadIdx.x & 31;
    int row = blockIdx.x * 4 + warp;
    const float* src = (mode == 0) ? (xin + (size_t)orig_index(row) * C_DIM)
                                   : (g_x1 + (size_t)row * C_DIM);
    float v[6];
    float s = 0.f, sq = 0.f;
#pragma unroll
    for (int k = 0; k < 6; k++) {
        v[k] = src[lane + 32 * k];
        s += v[k]; sq += v[k] * v[k];
    }
#pragma unroll
    for (int o = 16; o; o >>= 1) {
        s  += __shfl_xor_sync(0xffffffffu, s, o);
        sq += __shfl_xor_sync(0xffffffffu, sq, o);
    }
    float mean = s * (1.f / 192.f);
    float var  = sq * (1.f / 192.f) - mean * mean;
    float rstd = rsqrtf(var + 1e-5f);
    float* dst = g_xw + (size_t)row * C_DIM;
#pragma unroll
    for (int k = 0; k < 6; k++) {
        int d = lane + 32 * k;
        dst[d] = (v[k] - mean) * rstd * gg[d] + bb[d];
    }
}

// ---------------- window attention: block per window, warp per head --------
__global__ __launch_bounds__(192) void attn_kernel(const float* __restrict__ bias_table)
{
    __shared__ __align__(16) float kv[NHEADS * NWIN * HD];  // 24 KB: K then V per head
    __shared__ float bias_s[105 * NHEADS];
    __shared__ int   reg_s[NWIN];

    int tid  = threadIdx.x;
    int wid  = tid >> 5;       // head
    int lane = tid & 31;       // token i within window
    int win  = blockIdx.x;

    for (int i = tid; i < 105 * NHEADS; i += 192) bias_s[i] = bias_table[i];
    if (tid < NWIN) {
        int wloc = win & 1023;
        int iwh = wloc >> 6, iww = wloc & 63;
        int hs = iwh * 4 + (tid >> 3);
        int ws = iww * 8 + (tid & 7);
        reg_s[tid] = ((hs >= 62) ? 2 : 0) + ((ws >= 508) ? 1 : 0);
    }
    __syncthreads();

    float* kb = kv + wid * (NWIN * HD);
    const float* qkvw = g_qkv + (size_t)win * NWIN * C3;

    // stage K[32][32] for this head (coalesced, conflict-free)
#pragma unroll 4
    for (int j = 0; j < NWIN; j++)
        kb[j * HD + lane] = qkvw[j * C3 + C_DIM + wid * HD + lane];

    // q row for token i = lane, as f32x2 pairs
    ull q2[16];
    {
        const float4* qp = reinterpret_cast<const float4*>(qkvw + (size_t)lane * C3 + wid * HD);
#pragma unroll
        for (int d4 = 0; d4 < 8; d4++) {
            float4 t = qp[d4];
            q2[d4 * 2 + 0] = pack2(t.x, t.y);
            q2[d4 * 2 + 1] = pack2(t.z, t.w);
        }
    }
    __syncwarp();

    float sc[NWIN];
    int regi = reg_s[lane];
    int thi = lane >> 3, twi = lane & 7;
#pragma unroll 4
    for (int j = 0; j < NWIN; j++) {
        const ull* k2 = reinterpret_cast<const ull*>(kb + j * HD);
        ull s2 = 0ull;
#pragma unroll
        for (int dd = 0; dd < 16; dd++) s2 = fma2(q2[dd], k2[dd], s2);
        float lo, hi; unpack2(s2, lo, hi);
        float s = (lo + hi) * 0.17677669529663687f;     // hd^-0.5
        int dh = thi - (j >> 3) + 3;
        int dw = twi - (j & 7) + 7;
        s += bias_s[(dh * 15 + dw) * NHEADS + wid];
        if (regi != reg_s[j]) s -= 100.f;
        sc[j] = s;
    }

    float mx = sc[0];
#pragma unroll
    for (int j = 1; j < NWIN; j++) mx = fmaxf(mx, sc[j]);
    float sum = 0.f;
#pragma unroll
    for (int j = 0; j < NWIN; j++) { sc[j] = __expf(sc[j] - mx); sum += sc[j]; }
    float inv = 1.f / sum;

    // overwrite K buffer with V (warp-private region, warp-sync fenced)
    __syncwarp();
#pragma unroll 4
    for (int j = 0; j < NWIN; j++)
        kb[j * HD + lane] = qkvw[j * C3 + 2 * C_DIM + wid * HD + lane];
    __syncwarp();

    ull o2[16];
#pragma unroll
    for (int dd = 0; dd < 16; dd++) o2[dd] = 0ull;
#pragma unroll 4
    for (int j = 0; j < NWIN; j++) {
        float p = sc[j] * inv;
        ull p2 = pack2(p, p);
        const ull* v2 = reinterpret_cast<const ull*>(kb + j * HD);
#pragma unroll
        for (int dd = 0; dd < 16; dd++) o2[dd] = fma2(p2, v2[dd], o2[dd]);
    }

    ull* op = reinterpret_cast<ull*>(g_attn + (size_t)(win * NWIN + lane) * C_DIM + wid * HD);
#pragma unroll
    for (int dd = 0; dd < 16; dd++) op[dd] = o2[dd];
}

// ---------------- SGEMM: 128x64x16 tiles, 256 threads, 8x4 via f32x2 -------
// MODE 0: g_xw   @ w_qkv + b    -> g_qkv
// MODE 1: g_attn @ w_proj + b   -> scatter(orig) into g_x1 = x + .
// MODE 2: g_xw   @ w1 + b, gelu -> g_hid
// MODE 3: g_hid  @ w2 + b + x1  -> extout (d_out)
#define BM 128
#define BN 64
#define BK 16

template<int K, int N, int MODE>
__global__ __launch_bounds__(256) void sgemm_kernel(
    const float* __restrict__ Bw, const float* __restrict__ bias,
    const float* __restrict__ addsrc, float* __restrict__ extout)
{
    __shared__ __align__(16) float As[BK][BM + 4];
    __shared__ __align__(16) float Bs[BK][BN];

    const float* A = (MODE == 0 || MODE == 2) ? g_xw
                   : (MODE == 1) ? g_attn : g_hid;

    int tid = threadIdx.x;
    int tx = tid & 15;           // -> 4 cols
    int ty = tid >> 4;           // -> 8 rows
    int n0 = blockIdx.x * BN;    // N-tile fastest => A tile reused from L2
    int m0 = blockIdx.y * BM;

    ull acc[4][4];
#pragma unroll
    for (int i = 0; i < 4; i++)
#pragma unroll
        for (int j = 0; j < 4; j++) acc[i][j] = 0ull;

    int arow0 = tid >> 2;            // 0..63
    int ac4   = (tid & 3) * 4;       // 0,4,8,12
    int bk    = tid >> 4;            // 0..15
    int bc4   = (tid & 15) * 4;      // 0..60

    for (int k0 = 0; k0 < K; k0 += BK) {
#pragma unroll
        for (int r = 0; r < 2; r++) {
            int row = arow0 + r * 64;
            float4 v = *reinterpret_cast<const float4*>(&A[(size_t)(m0 + row) * K + k0 + ac4]);
            As[ac4 + 0][row] = v.x; As[ac4 + 1][row] = v.y;
            As[ac4 + 2][row] = v.z; As[ac4 + 3][row] = v.w;
        }
        *reinterpret_cast<float4*>(&Bs[bk][bc4]) =
            *reinterpret_cast<const float4*>(&Bw[(size_t)(k0 + bk) * N + n0 + bc4]);
        __syncthreads();

#pragma unroll
        for (int k = 0; k < BK; k++) {
            const ull* a2 = reinterpret_cast<const ull*>(&As[k][ty * 8]);
            float4 bq = *reinterpret_cast<const float4*>(&Bs[k][tx * 4]);
            ull b2[4];
            b2[0] = pack2(bq.x, bq.x); b2[1] = pack2(bq.y, bq.y);
            b2[2] = pack2(bq.z, bq.z); b2[3] = pack2(bq.w, bq.w);
            ull av[4];
            av[0] = a2[0]; av[1] = a2[1]; av[2] = a2[2]; av[3] = a2[3];
#pragma unroll
            for (int i = 0; i < 4; i++)
#pragma unroll
                for (int j = 0; j < 4; j++)
                    acc[i][j] = fma2(av[i], b2[j], acc[i][j]);
        }
        __syncthreads();
    }

    float cf[8][4];
#pragma unroll
    for (int i = 0; i < 4; i++)
#pragma unroll
        for (int j = 0; j < 4; j++)
            unpack2(acc[i][j], cf[2 * i][j], cf[2 * i + 1][j]);

#pragma unroll
    for (int i = 0; i < 8; i++) {
        int m = m0 + ty * 8 + i;
        if (MODE == 1) {
            int o = orig_index(m);
#pragma unroll
            for (int j = 0; j < 4; j++) {
                int n = n0 + tx * 4 + j;
                float v = cf[i][j] + bias[n];
                g_x1[(size_t)o * C_DIM + n] = addsrc[(size_t)o * C_DIM + n] + v;
            }
        } else {
#pragma unroll
            for (int j = 0; j < 4; j++) {
                int n = n0 + tx * 4 + j;
                float v = cf[i][j] + bias[n];
                if (MODE == 0) {
                    g_qkv[(size_t)m * N + n] = v;
                } else if (MODE == 2) {
                    g_hid[(size_t)m * N + n] = 0.5f * v * (1.f + erff(v * 0.70710678118654752f));
                } else { // MODE 3
                    extout[(size_t)m * N + n] = v + g_x1[(size_t)m * N + n];
                }
            }
        }
    }
}

// ---------------- launch ----------------
extern "C" void kernel_launch(void* const* d_in, const int* in_sizes, int n_in,
                              void* d_out, int out_size)
{
    const float* x          = (const float*)d_in[0];
    // d_in[1], d_in[2] = H, W scalars (static: 64, 512)
    const float* g1         = (const float*)d_in[3];
    const float* be1        = (const float*)d_in[4];
    const float* w_qkv      = (const float*)d_in[5];
    const float* b_qkv      = (const float*)d_in[6];
    const float* w_proj     = (const float*)d_in[7];
    const float* b_proj     = (const float*)d_in[8];
    const float* bias_table = (const float*)d_in[9];
    const float* g2         = (const float*)d_in[10];
    const float* be2        = (const float*)d_in[11];
    const float* w1         = (const float*)d_in[12];
    const float* bm1        = (const float*)d_in[13];
    const float* w2         = (const float*)d_in[14];
    const float* bm2        = (const float*)d_in[15];
    float* out = (float*)d_out;

    // 1. shifted-window gather + LN1 -> g_xw (window-major rows)
    ln_kernel<<<M_TOK / 4, 128>>>(x, g1, be1, 0);

    // 2. QKV GEMM: g_xw[262144,192] @ w_qkv[192,576] -> g_qkv
    sgemm_kernel<192, 576, 0><<<dim3(576 / BN, M_TOK / BM), 256>>>(w_qkv, b_qkv, nullptr, nullptr);

    // 3. windowed attention (bias + shift mask + softmax) -> g_attn
    attn_kernel<<<M_TOK / NWIN, 192>>>(bias_table);

    // 4. proj GEMM + window-reverse scatter + residual -> g_x1 = x + attn
    sgemm_kernel<192, 192, 1><<<dim3(192 / BN, M_TOK / BM), 256>>>(w_proj, b_proj, x, nullptr);

    // 5. LN2(x1) -> g_xw (token-major rows)
    ln_kernel<<<M_TOK / 4, 128>>>(x, g2, be2, 1);

    // 6. MLP1 GEMM + exact GELU -> g_hid
    sgemm_kernel<192, 768, 2><<<dim3(768 / BN, M_TOK / BM), 256>>>(w1, bm1, nullptr, nullptr);

    // 7. MLP2 GEMM + bias + residual(x1) -> d_out
    sgemm_kernel<768, 192, 3><<<dim3(192 / BN, M_TOK / BM), 256>>>(w2, bm2, nullptr, out);

    (void)in_sizes; (void)n_in; (void)out_size;
}

// round 15
// speedup vs baseline: 1.0018x; 1.0018x over previous
#include <cuda_runtime.h>

typedef unsigned long long ull;

// ---------------- static problem config ----------------
#define M_TOK   262144      // 8 * 64 * 512 tokens
#define C_DIM   192
#define C3      576         // 3*C
#define HID     768
#define NHEADS  6
#define HD      32
#define NWIN    32          // 4*8 tokens per window

// ---------------- scratch (module-load allocated, ~2 GB) ----------------
__device__ float g_xw  [(size_t)M_TOK * C_DIM];   // LN1(win) and later LN2(x1)
__device__ float g_qkv [(size_t)M_TOK * C3];
__device__ float g_attn[(size_t)M_TOK * C_DIM];
__device__ float g_x1  [(size_t)M_TOK * C_DIM];
__device__ float g_hid [(size_t)M_TOK * HID];

// ---------------- packed f32x2 helpers (B300 FFMA2 path) ----------------
__device__ __forceinline__ ull pack2(float lo, float hi) {
    ull r;
    asm("mov.b64 %0, {%1, %2};" : "=l"(r) : "f"(lo), "f"(hi));
    return r;
}
__device__ __forceinline__ void unpack2(ull v, float& lo, float& hi) {
    asm("mov.b64 {%0, %1}, %2;" : "=f"(lo), "=f"(hi) : "l"(v));
}
__device__ __forceinline__ ull fma2(ull a, ull b, ull c) {
    ull r;
    asm("fma.rn.f32x2 %0, %1, %2, %3;" : "=l"(r) : "l"(a), "l"(b), "l"(c));
    return r;
}

// window-layout row m  ->  original token index (shift gather == scatter map)
__device__ __forceinline__ int orig_index(int m) {
    int bb  = m >> 15;          // / 32768 tokens per batch
    int rem = m & 32767;
    int wloc = rem >> 5;        // window within batch (0..1023)
    int t    = rem & 31;        // token within window
    int iwh = wloc >> 6;        // 0..15
    int iww = wloc & 63;        // 0..63
    int hs = iwh * 4 + (t >> 3);
    int ws = iww * 8 + (t & 7);
    int h = hs + 2; if (h >= 64)  h -= 64;
    int w = ws + 4; if (w >= 512) w -= 512;
    return (bb << 15) + (h << 9) + w;
}

// ---------------- LayerNorm (warp per row), optional shifted-window gather --
// mode 0: dst row = window layout, src = xin[orig_index(row)]   (LN1)
// mode 1: dst row = token layout,  src = g_x1[row]              (LN2)
__global__ __launch_bounds__(128) void ln_kernel(
    const float* __restrict__ xin, const float* __restrict__ gg,
    const float* __restrict__ bb, int mode)
{
    int warp = threadIdx.x >> 5;
    int lane = threadIdx.x & 31;
    int row = blockIdx.x * 4 + warp;
    const float* src = (mode == 0) ? (xin + (size_t)orig_index(row) * C_DIM)
                                   : (g_x1 + (size_t)row * C_DIM);
    float v[6];
    float s = 0.f, sq = 0.f;
#pragma unroll
    for (int k = 0; k < 6; k++) {
        v[k] = src[lane + 32 * k];
        s += v[k]; sq += v[k] * v[k];
    }
#pragma unroll
    for (int o = 16; o; o >>= 1) {
        s  += __shfl_xor_sync(0xffffffffu, s, o);
        sq += __shfl_xor_sync(0xffffffffu, sq, o);
    }
    float mean = s * (1.f / 192.f);
    float var  = sq * (1.f / 192.f) - mean * mean;
    float rstd = rsqrtf(var + 1e-5f);
    float* dst = g_xw + (size_t)row * C_DIM;
#pragma unroll
    for (int k = 0; k < 6; k++) {
        int d = lane + 32 * k;
        dst[d] = (v[k] - mean) * rstd * gg[d] + bb[d];
    }
}

// ---------------- window attention: block per window, warp per head --------
__global__ __launch_bounds__(192) void attn_kernel(const float* __restrict__ bias_table)
{
    __shared__ __align__(16) float kv[NHEADS * NWIN * HD];  // 24 KB: K then V per head
    __shared__ float bias_s[105 * NHEADS];
    __shared__ int   reg_s[NWIN];

    int tid  = threadIdx.x;
    int wid  = tid >> 5;       // head
    int lane = tid & 31;       // token i within window
    int win  = blockIdx.x;

    for (int i = tid; i < 105 * NHEADS; i += 192) bias_s[i] = bias_table[i];
    if (tid < NWIN) {
        int wloc = win & 1023;
        int iwh = wloc >> 6, iww = wloc & 63;
        int hs = iwh * 4 + (tid >> 3);
        int ws = iww * 8 + (tid & 7);
        reg_s[tid] = ((hs >= 62) ? 2 : 0) + ((ws >= 508) ? 1 : 0);
    }
    __syncthreads();

    float* kb = kv + wid * (NWIN * HD);
    const float* qkvw = g_qkv + (size_t)win * NWIN * C3;

    // stage K[32][32] for this head (coalesced, conflict-free)
#pragma unroll 4
    for (int j = 0; j < NWIN; j++)
        kb[j * HD + lane] = qkvw[j * C3 + C_DIM + wid * HD + lane];

    // q row for token i = lane, as f32x2 pairs
    ull q2[16];
    {
        const float4* qp = reinterpret_cast<const float4*>(qkvw + (size_t)lane * C3 + wid * HD);
#pragma unroll
        for (int d4 = 0; d4 < 8; d4++) {
            float4 t = qp[d4];
            q2[d4 * 2 + 0] = pack2(t.x, t.y);
            q2[d4 * 2 + 1] = pack2(t.z, t.w);
        }
    }
    __syncwarp();

    float sc[NWIN];
    int regi = reg_s[lane];
    int thi = lane >> 3, twi = lane & 7;
#pragma unroll 4
    for (int j = 0; j < NWIN; j++) {
        const ull* k2 = reinterpret_cast<const ull*>(kb + j * HD);
        ull s2 = 0ull;
#pragma unroll
        for (int dd = 0; dd < 16; dd++) s2 = fma2(q2[dd], k2[dd], s2);
        float lo, hi; unpack2(s2, lo, hi);
        float s = (lo + hi) * 0.17677669529663687f;     // hd^-0.5
        int dh = thi - (j >> 3) + 3;
        int dw = twi - (j & 7) + 7;
        s += bias_s[(dh * 15 + dw) * NHEADS + wid];
        if (regi != reg_s[j]) s -= 100.f;
        sc[j] = s;
    }

    float mx = sc[0];
#pragma unroll
    for (int j = 1; j < NWIN; j++) mx = fmaxf(mx, sc[j]);
    float sum = 0.f;
#pragma unroll
    for (int j = 0; j < NWIN; j++) { sc[j] = __expf(sc[j] - mx); sum += sc[j]; }
    float inv = 1.f / sum;

    // overwrite K buffer with V (warp-private region, warp-sync fenced)
    __syncwarp();
#pragma unroll 4
    for (int j = 0; j < NWIN; j++)
        kb[j * HD + lane] = qkvw[j * C3 + 2 * C_DIM + wid * HD + lane];
    __syncwarp();

    ull o2[16];
#pragma unroll
    for (int dd = 0; dd < 16; dd++) o2[dd] = 0ull;
#pragma unroll 4
    for (int j = 0; j < NWIN; j++) {
        float p = sc[j] * inv;
        ull p2 = pack2(p, p);
        const ull* v2 = reinterpret_cast<const ull*>(kb + j * HD);
#pragma unroll
        for (int dd = 0; dd < 16; dd++) o2[dd] = fma2(p2, v2[dd], o2[dd]);
    }

    ull* op = reinterpret_cast<ull*>(g_attn + (size_t)(win * NWIN + lane) * C_DIM + wid * HD);
#pragma unroll
    for (int dd = 0; dd < 16; dd++) op[dd] = o2[dd];
}

// ---------------- SGEMM: 128x64x16 tiles, 256 threads, 8x4 via f32x2 -------
// MODE 0: g_xw   @ w_qkv + b    -> g_qkv
// MODE 1: g_attn @ w_proj + b   -> scatter(orig) into g_x1 = x + .
// MODE 2: g_xw   @ w1 + b, gelu -> g_hid
// MODE 3: g_hid  @ w2 + b + x1  -> extout (d_out)
#define BM 128
#define BN 64
#define BK 16

template<int K, int N, int MODE>
__global__ __launch_bounds__(256) void sgemm_kernel(
    const float* __restrict__ Bw, const float* __restrict__ bias,
    const float* __restrict__ addsrc, float* __restrict__ extout)
{
    __shared__ __align__(16) float As[BK][BM + 4];
    __shared__ __align__(16) float Bs[BK][BN];

    const float* A = (MODE == 0 || MODE == 2) ? g_xw
                   : (MODE == 1) ? g_attn : g_hid;

    int tid = threadIdx.x;
    int tx = tid & 15;           // -> 4 cols
    int ty = tid >> 4;           // -> 8 rows
    int n0 = blockIdx.x * BN;    // N-tile fastest => A tile reused from L2
    int m0 = blockIdx.y * BM;

    ull acc[4][4];
#pragma unroll
    for (int i = 0; i < 4; i++)
#pragma unroll
        for (int j = 0; j < 4; j++) acc[i][j] = 0ull;

    int arow0 = tid >> 2;            // 0..63
    int ac4   = (tid & 3) * 4;       // 0,4,8,12
    int bk    = tid >> 4;            // 0..15
    int bc4   = (tid & 15) * 4;      // 0..60

    for (int k0 = 0; k0 < K; k0 += BK) {
#pragma unroll
        for (int r = 0; r < 2; r++) {
            int row = arow0 + r * 64;
            float4 v = *reinterpret_cast<const float4*>(&A[(size_t)(m0 + row) * K + k0 + ac4]);
            As[ac4 + 0][row] = v.x; As[ac4 + 1][row] = v.y;
            As[ac4 + 2][row] = v.z; As[ac4 + 3][row] = v.w;
        }
        *reinterpret_cast<float4*>(&Bs[bk][bc4]) =
            *reinterpret_cast<const float4*>(&Bw[(size_t)(k0 + bk) * N + n0 + bc4]);
        __syncthreads();

#pragma unroll
        for (int k = 0; k < BK; k++) {
            const ull* a2 = reinterpret_cast<const ull*>(&As[k][ty * 8]);
            float4 bq = *reinterpret_cast<const float4*>(&Bs[k][tx * 4]);
            ull b2[4];
            b2[0] = pack2(bq.x, bq.x); b2[1] = pack2(bq.y, bq.y);
            b2[2] = pack2(bq.z, bq.z); b2[3] = pack2(bq.w, bq.w);
            ull av[4];
            av[0] = a2[0]; av[1] = a2[1]; av[2] = a2[2]; av[3] = a2[3];
#pragma unroll
            for (int i = 0; i < 4; i++)
#pragma unroll
                for (int j = 0; j < 4; j++)
                    acc[i][j] = fma2(av[i], b2[j], acc[i][j]);
        }
        __syncthreads();
    }

    float cf[8][4];
#pragma unroll
    for (int i = 0; i < 4; i++)
#pragma unroll
        for (int j = 0; j < 4; j++)
            unpack2(acc[i][j], cf[2 * i][j], cf[2 * i + 1][j]);

#pragma unroll
    for (int i = 0; i < 8; i++) {
        int m = m0 + ty * 8 + i;
        if (MODE == 1) {
            int o = orig_index(m);
#pragma unroll
            for (int j = 0; j < 4; j++) {
                int n = n0 + tx * 4 + j;
                float v = cf[i][j] + bias[n];
                g_x1[(size_t)o * C_DIM + n] = addsrc[(size_t)o * C_DIM + n] + v;
            }
        } else {
#pragma unroll
            for (int j = 0; j < 4; j++) {
                int n = n0 + tx * 4 + j;
                float v = cf[i][j] + bias[n];
                if (MODE == 0) {
                    g_qkv[(size_t)m * N + n] = v;
                } else if (MODE == 2) {
                    g_hid[(size_t)m * N + n] = 0.5f * v * (1.f + erff(v * 0.70710678118654752f));
                } else { // MODE 3
                    extout[(size_t)m * N + n] = v + g_x1[(size_t)m * N + n];
                }
            }
        }
    }
}

// ---------------- launch ----------------
extern "C" void kernel_launch(void* const* d_in, const int* in_sizes, int n_in,
                              void* d_out, int out_size)
{
    const float* x          = (const float*)d_in[0];
    // d_in[1], d_in[2] = H, W scalars (static: 64, 512)
    const float* g1         = (const float*)d_in[3];
    const float* be1        = (const float*)d_in[4];
    const float* w_qkv      = (const float*)d_in[5];
    const float* b_qkv      = (const float*)d_in[6];
    const float* w_proj     = (const float*)d_in[7];
    const float* b_proj     = (const float*)d_in[8];
    const float* bias_table = (const float*)d_in[9];
    const float* g2         = (const float*)d_in[10];
    const float* be2        = (const float*)d_in[11];
    const float* w1         = (const float*)d_in[12];
    const float* bm1        = (const float*)d_in[13];
    const float* w2         = (const float*)d_in[14];
    const float* bm2        = (const float*)d_in[15];
    float* out = (float*)d_out;

    // 1. shifted-window gather + LN1 -> g_xw (window-major rows)
    ln_kernel<<<M_TOK / 4, 128>>>(x, g1, be1, 0);

    // 2. QKV GEMM: g_xw[262144,192] @ w_qkv[192,576] -> g_qkv
    sgemm_kernel<192, 576, 0><<<dim3(576 / BN, M_TOK / BM), 256>>>(w_qkv, b_qkv, nullptr, nullptr);

    // 3. windowed attention (bias + shift mask + softmax) -> g_attn
    attn_kernel<<<M_TOK / NWIN, 192>>>(bias_table);

    // 4. proj GEMM + window-reverse scatter + residual -> g_x1 = x + attn
    sgemm_kernel<192, 192, 1><<<dim3(192 / BN, M_TOK / BM), 256>>>(w_proj, b_proj, x, nullptr);

    // 5. LN2(x1) -> g_xw (token-major rows)
    ln_kernel<<<M_TOK / 4, 128>>>(x, g2, be2, 1);

    // 6. MLP1 GEMM + exact GELU -> g_hid
    sgemm_kernel<192, 768, 2><<<dim3(768 / BN, M_TOK / BM), 256>>>(w1, bm1, nullptr, nullptr);

    // 7. MLP2 GEMM + bias + residual(x1) -> d_out
    sgemm_kernel<768, 192, 3><<<dim3(192 / BN, M_TOK / BM), 256>>>(w2, bm2, nullptr, out);

    (void)in_sizes; (void)n_in; (void)out_size;
}

// round 16
// speedup vs baseline: 1.0023x; 1.0005x over previous
#include <cuda_runtime.h>

typedef unsigned long long ull;

// ---------------- static problem config ----------------
#define M_TOK   262144      // 8 * 64 * 512 tokens
#define C_DIM   192
#define C3      576         // 3*C
#define HID     768
#define NHEADS  6
#define HD      32
#define NWIN    32          // 4*8 tokens per window

// ---------------- scratch (module-load allocated, ~2 GB) ----------------
__device__ float g_xw  [(size_t)M_TOK * C_DIM];   // LN1(win) and later LN2(x1)
__device__ float g_qkv [(size_t)M_TOK * C3];
__device__ float g_attn[(size_t)M_TOK * C_DIM];
__device__ float g_x1  [(size_t)M_TOK * C_DIM];
__device__ float g_hid [(size_t)M_TOK * HID];

// ---------------- packed f32x2 helpers (B300 FFMA2 path) ----------------
__device__ __forceinline__ ull pack2(float lo, float hi) {
    ull r;
    asm("mov.b64 %0, {%1, %2};" : "=l"(r) : "f"(lo), "f"(hi));
    return r;
}
__device__ __forceinline__ void unpack2(ull v, float& lo, float& hi) {
    asm("mov.b64 {%0, %1}, %2;" : "=f"(lo), "=f"(hi) : "l"(v));
}
__device__ __forceinline__ ull fma2(ull a, ull b, ull c) {
    ull r;
    asm("fma.rn.f32x2 %0, %1, %2, %3;" : "=l"(r) : "l"(a), "l"(b), "l"(c));
    return r;
}

// window-layout row m  ->  original token index (shift gather == scatter map)
__device__ __forceinline__ int orig_index(int m) {
    int bb  = m >> 15;          // / 32768 tokens per batch
    int rem = m & 32767;
    int wloc = rem >> 5;        // window within batch (0..1023)
    int t    = rem & 31;        // token within window
    int iwh = wloc >> 6;        // 0..15
    int iww = wloc & 63;        // 0..63
    int hs = iwh * 4 + (t >> 3);
    int ws = iww * 8 + (t & 7);
    int h = hs + 2; if (h >= 64)  h -= 64;
    int w = ws + 4; if (w >= 512) w -= 512;
    return (bb << 15) + (h << 9) + w;
}

// ---------------- LayerNorm (warp per row), optional shifted-window gather --
// mode 0: dst row = window layout, src = xin[orig_index(row)]   (LN1)
// mode 1: dst row = token layout,  src = g_x1[row]              (LN2)
__global__ __launch_bounds__(128) void ln_kernel(
    const float* __restrict__ xin, const float* __restrict__ gg,
    const float* __restrict__ bb, int mode)
{
    int warp = threadIdx.x >> 5;
    int lane = threadIdx.x & 31;
    int row = blockIdx.x * 4 + warp;
    const float* src = (mode == 0) ? (xin + (size_t)orig_index(row) * C_DIM)
                                   : (g_x1 + (size_t)row * C_DIM);
    float v[6];
    float s = 0.f, sq = 0.f;
#pragma unroll
    for (int k = 0; k < 6; k++) {
        v[k] = src[lane + 32 * k];
        s += v[k]; sq += v[k] * v[k];
    }
#pragma unroll
    for (int o = 16; o; o >>= 1) {
        s  += __shfl_xor_sync(0xffffffffu, s, o);
        sq += __shfl_xor_sync(0xffffffffu, sq, o);
    }
    float mean = s * (1.f / 192.f);
    float var  = sq * (1.f / 192.f) - mean * mean;
    float rstd = rsqrtf(var + 1e-5f);
    float* dst = g_xw + (size_t)row * C_DIM;
#pragma unroll
    for (int k = 0; k < 6; k++) {
        int d = lane + 32 * k;
        dst[d] = (v[k] - mean) * rstd * gg[d] + bb[d];
    }
}

// ---------------- window attention: block per window, warp per head --------
__global__ __launch_bounds__(192) void attn_kernel(const float* __restrict__ bias_table)
{
    __shared__ __align__(16) float kv[NHEADS * NWIN * HD];  // 24 KB: K then V per head
    __shared__ float bias_s[105 * NHEADS];
    __shared__ int   reg_s[NWIN];

    int tid  = threadIdx.x;
    int wid  = tid >> 5;       // head
    int lane = tid & 31;       // token i within window
    int win  = blockIdx.x;

    for (int i = tid; i < 105 * NHEADS; i += 192) bias_s[i] = bias_table[i];
    if (tid < NWIN) {
        int wloc = win & 1023;
        int iwh = wloc >> 6, iww = wloc & 63;
        int hs = iwh * 4 + (tid >> 3);
        int ws = iww * 8 + (tid & 7);
        reg_s[tid] = ((hs >= 62) ? 2 : 0) + ((ws >= 508) ? 1 : 0);
    }
    __syncthreads();

    float* kb = kv + wid * (NWIN * HD);
    const float* qkvw = g_qkv + (size_t)win * NWIN * C3;

    // stage K[32][32] for this head (coalesced, conflict-free)
#pragma unroll 4
    for (int j = 0; j < NWIN; j++)
        kb[j * HD + lane] = qkvw[j * C3 + C_DIM + wid * HD + lane];

    // q row for token i = lane, as f32x2 pairs
    ull q2[16];
    {
        const float4* qp = reinterpret_cast<const float4*>(qkvw + (size_t)lane * C3 + wid * HD);
#pragma unroll
        for (int d4 = 0; d4 < 8; d4++) {
            float4 t = qp[d4];
            q2[d4 * 2 + 0] = pack2(t.x, t.y);
            q2[d4 * 2 + 1] = pack2(t.z, t.w);
        }
    }
    __syncwarp();

    float sc[NWIN];
    int regi = reg_s[lane];
    int thi = lane >> 3, twi = lane & 7;
#pragma unroll 4
    for (int j = 0; j < NWIN; j++) {
        const ull* k2 = reinterpret_cast<const ull*>(kb + j * HD);
        ull s2 = 0ull;
#pragma unroll
        for (int dd = 0; dd < 16; dd++) s2 = fma2(q2[dd], k2[dd], s2);
        float lo, hi; unpack2(s2, lo, hi);
        float s = (lo + hi) * 0.17677669529663687f;     // hd^-0.5
        int dh = thi - (j >> 3) + 3;
        int dw = twi - (j & 7) + 7;
        s += bias_s[(dh * 15 + dw) * NHEADS + wid];
        if (regi != reg_s[j]) s -= 100.f;
        sc[j] = s;
    }

    float mx = sc[0];
#pragma unroll
    for (int j = 1; j < NWIN; j++) mx = fmaxf(mx, sc[j]);
    float sum = 0.f;
#pragma unroll
    for (int j = 0; j < NWIN; j++) { sc[j] = __expf(sc[j] - mx); sum += sc[j]; }
    float inv = 1.f / sum;

    // overwrite K buffer with V (warp-private region, warp-sync fenced)
    __syncwarp();
#pragma unroll 4
    for (int j = 0; j < NWIN; j++)
        kb[j * HD + lane] = qkvw[j * C3 + 2 * C_DIM + wid * HD + lane];
    __syncwarp();

    ull o2[16];
#pragma unroll
    for (int dd = 0; dd < 16; dd++) o2[dd] = 0ull;
#pragma unroll 4
    for (int j = 0; j < NWIN; j++) {
        float p = sc[j] * inv;
        ull p2 = pack2(p, p);
        const ull* v2 = reinterpret_cast<const ull*>(kb + j * HD);
#pragma unroll
        for (int dd = 0; dd < 16; dd++) o2[dd] = fma2(p2, v2[dd], o2[dd]);
    }

    ull* op = reinterpret_cast<ull*>(g_attn + (size_t)(win * NWIN + lane) * C_DIM + wid * HD);
#pragma unroll
    for (int dd = 0; dd < 16; dd++) op[dd] = o2[dd];
}

// ---------------- SGEMM: 128x64x16 tiles, 256 threads, 8x4 via f32x2 -------
// MODE 0: g_xw   @ w_qkv + b    -> g_qkv
// MODE 1: g_attn @ w_proj + b   -> scatter(orig) into g_x1 = x + .
// MODE 2: g_xw   @ w1 + b, gelu -> g_hid
// MODE 3: g_hid  @ w2 + b + x1  -> extout (d_out)
#define BM 128
#define BN 64
#define BK 16

template<int K, int N, int MODE>
__global__ __launch_bounds__(256) void sgemm_kernel(
    const float* __restrict__ Bw, const float* __restrict__ bias,
    const float* __restrict__ addsrc, float* __restrict__ extout)
{
    __shared__ __align__(16) float As[BK][BM + 4];
    __shared__ __align__(16) float Bs[BK][BN];

    const float* A = (MODE == 0 || MODE == 2) ? g_xw
                   : (MODE == 1) ? g_attn : g_hid;

    int tid = threadIdx.x;
    int tx = tid & 15;           // -> 4 cols
    int ty = tid >> 4;           // -> 8 rows
    int n0 = blockIdx.x * BN;    // N-tile fastest => A tile reused from L2
    int m0 = blockIdx.y * BM;

    ull acc[4][4];
#pragma unroll
    for (int i = 0; i < 4; i++)
#pragma unroll
        for (int j = 0; j < 4; j++) acc[i][j] = 0ull;

    int arow0 = tid >> 2;            // 0..63
    int ac4   = (tid & 3) * 4;       // 0,4,8,12
    int bk    = tid >> 4;            // 0..15
    int bc4   = (tid & 15) * 4;      // 0..60

    for (int k0 = 0; k0 < K; k0 += BK) {
#pragma unroll
        for (int r = 0; r < 2; r++) {
            int row = arow0 + r * 64;
            float4 v = *reinterpret_cast<const float4*>(&A[(size_t)(m0 + row) * K + k0 + ac4]);
            As[ac4 + 0][row] = v.x; As[ac4 + 1][row] = v.y;
            As[ac4 + 2][row] = v.z; As[ac4 + 3][row] = v.w;
        }
        *reinterpret_cast<float4*>(&Bs[bk][bc4]) =
            *reinterpret_cast<const float4*>(&Bw[(size_t)(k0 + bk) * N + n0 + bc4]);
        __syncthreads();

#pragma unroll
        for (int k = 0; k < BK; k++) {
            const ull* a2 = reinterpret_cast<const ull*>(&As[k][ty * 8]);
            float4 bq = *reinterpret_cast<const float4*>(&Bs[k][tx * 4]);
            ull b2[4];
            b2[0] = pack2(bq.x, bq.x); b2[1] = pack2(bq.y, bq.y);
            b2[2] = pack2(bq.z, bq.z); b2[3] = pack2(bq.w, bq.w);
            ull av[4];
            av[0] = a2[0]; av[1] = a2[1]; av[2] = a2[2]; av[3] = a2[3];
#pragma unroll
            for (int i = 0; i < 4; i++)
#pragma unroll
                for (int j = 0; j < 4; j++)
                    acc[i][j] = fma2(av[i], b2[j], acc[i][j]);
        }
        __syncthreads();
    }

    float cf[8][4];
#pragma unroll
    for (int i = 0; i < 4; i++)
#pragma unroll
        for (int j = 0; j < 4; j++)
            unpack2(acc[i][j], cf[2 * i][j], cf[2 * i + 1][j]);

#pragma unroll
    for (int i = 0; i < 8; i++) {
        int m = m0 + ty * 8 + i;
        if (MODE == 1) {
            int o = orig_index(m);
#pragma unroll
            for (int j = 0; j < 4; j++) {
                int n = n0 + tx * 4 + j;
                float v = cf[i][j] + bias[n];
                g_x1[(size_t)o * C_DIM + n] = addsrc[(size_t)o * C_DIM + n] + v;
            }
        } else {
#pragma unroll
            for (int j = 0; j < 4; j++) {
                int n = n0 + tx * 4 + j;
                float v = cf[i][j] + bias[n];
                if (MODE == 0) {
                    g_qkv[(size_t)m * N + n] = v;
                } else if (MODE == 2) {
                    g_hid[(size_t)m * N + n] = 0.5f * v * (1.f + erff(v * 0.70710678118654752f));
                } else { // MODE 3
                    extout[(size_t)m * N + n] = v + g_x1[(size_t)m * N + n];
                }
            }
        }
    }
}

// ---------------- launch ----------------
extern "C" void kernel_launch(void* const* d_in, const int* in_sizes, int n_in,
                              void* d_out, int out_size)
{
    const float* x          = (const float*)d_in[0];
    // d_in[1], d_in[2] = H, W scalars (static: 64, 512)
    const float* g1         = (const float*)d_in[3];
    const float* be1        = (const float*)d_in[4];
    const float* w_qkv      = (const float*)d_in[5];
    const float* b_qkv      = (const float*)d_in[6];
    const float* w_proj     = (const float*)d_in[7];
    const float* b_proj     = (const float*)d_in[8];
    const float* bias_table = (const float*)d_in[9];
    const float* g2         = (const float*)d_in[10];
    const float* be2        = (const float*)d_in[11];
    const float* w1         = (const float*)d_in[12];
    const float* bm1        = (const float*)d_in[13];
    const float* w2         = (const float*)d_in[14];
    const float* bm2        = (const float*)d_in[15];
    float* out = (float*)d_out;

    // 1. shifted-window gather + LN1 -> g_xw (window-major rows)
    ln_kernel<<<M_TOK / 4, 128>>>(x, g1, be1, 0);

    // 2. QKV GEMM: g_xw[262144,192] @ w_qkv[192,576] -> g_qkv
    sgemm_kernel<192, 576, 0><<<dim3(576 / BN, M_TOK / BM), 256>>>(w_qkv, b_qkv, nullptr, nullptr);

    // 3. windowed attention (bias + shift mask + softmax) -> g_attn
    attn_kernel<<<M_TOK / NWIN, 192>>>(bias_table);

    // 4. proj GEMM + window-reverse scatter + residual -> g_x1 = x + attn
    sgemm_kernel<192, 192, 1><<<dim3(192 / BN, M_TOK / BM), 256>>>(w_proj, b_proj, x, nullptr);

    // 5. LN2(x1) -> g_xw (token-major rows)
    ln_kernel<<<M_TOK / 4, 128>>>(x, g2, be2, 1);

    // 6. MLP1 GEMM + exact GELU -> g_hid
    sgemm_kernel<192, 768, 2><<<dim3(768 / BN, M_TOK / BM), 256>>>(w1, bm1, nullptr, nullptr);

    // 7. MLP2 GEMM + bias + residual(x1) -> d_out
    sgemm_kernel<768, 192, 3><<<dim3(192 / BN, M_TOK / BM), 256>>>(w2, bm2, nullptr, out);

    (void)in_sizes; (void)n_in; (void)out_size;
}